// round 15
// baseline (speedup 1.0000x reference)
#include <cuda_runtime.h>
#include <cstdint>

#define CIN 4
#define COUT 8
#define HH 512
#define WW 512

// Prepacked weights: [half][c][ky][kx][qq][i][j] -> float2 (group g0, group g1 rows)
// Lane pairing: f32x2 lanes = output channels (co4=qq, co4=qq+2) which share
// weight-row o = qq*4+2i+j but read consecutive input columns (cj=0, cj=1).
__device__ float2 g_wpk[576];

__global__ void prepack_kernel(const float* __restrict__ w) {
    int idx = threadIdx.x;
    if (idx >= 576) return;
    int j  = idx & 1;
    int u  = idx >> 1;
    int i  = u & 1;  u >>= 1;
    int qq = u & 1;  u >>= 1;
    int kx = u % 3;  u /= 3;
    int ky = u % 3;  u /= 3;
    int c  = u & 3;  u >>= 2;
    int half = u;                        // 0 or 1
    int g0 = half * 2;
    int g1 = half * 2 + 1;
    int o  = qq * 4 + 2 * i + j;         // weight row within group
    int ct = c * 9 + ky * 3 + kx;
    float2 val;
    val.x = w[(g0 * 8 + o) * 36 + ct];   // lane lo: co4=qq   (cj=0)
    val.y = w[(g1 * 8 + o) * 36 + ct];   // lane hi: co4=qq+2 (cj=1)
    g_wpk[idx] = val;
}

__device__ __forceinline__ unsigned long long pack2(float a, float b) {
    unsigned long long r;
    asm("mov.b64 %0, {%1, %2};" : "=l"(r) : "f"(a), "f"(b));
    return r;
}
__device__ __forceinline__ void unpack2(unsigned long long p, float& a, float& b) {
    asm("mov.b64 {%0, %1}, %2;" : "=f"(a), "=f"(b) : "l"(p));
}
__device__ __forceinline__ void ffma2(unsigned long long& d, unsigned long long a, unsigned long long b) {
    asm("fma.rn.f32x2 %0, %1, %2, %0;" : "+l"(d) : "l"(a), "l"(b));
}

__global__ __launch_bounds__(128, 5)
void conv_kernel(const float* __restrict__ x, float* __restrict__ out) {
    __shared__ __align__(16) float2 ws[288];
    int tid = threadIdx.x;
    int lane = tid & 31;

    int half  = blockIdx.x & 1;               // channel half (co>>2)
    int hpair = (blockIdx.x >> 1) & 127;      // tile-row pair 0..127
    int b     = blockIdx.x >> 8;              // batch 0..7

    // Load this half's weights (288 float2 = 2.25 KB)
    {
        const float2* src = g_wpk + half * 288;
        for (int k = tid; k < 288; k += 128) ws[k] = src[k];
    }
    __syncthreads();

    int tx   = tid & 63;                      // 64 threads span one tile-row
    int hsub = tid >> 6;                      // 2 tile-rows per block
    int h    = hpair * 2 + hsub;              // tile row 0..255
    int x0   = tx << 3;                       // 8 output/input columns per thread

    const float* xb = x + (size_t)b * (CIN * HH * WW);
    float*       ob = out + (size_t)b * (COUT * HH * WW);

    // acc[t][qq][i][j] = f32x2 with lanes (co4=qq, co4=qq+2), out col x0+2t+j, row 2h+i
    unsigned long long acc[4][2][2][2];
    #pragma unroll
    for (int t = 0; t < 4; t++)
        #pragma unroll
        for (int qq = 0; qq < 2; qq++)
            #pragma unroll
            for (int i = 0; i < 2; i++) {
                acc[t][qq][i][0] = 0ULL;
                acc[t][qq][i][1] = 0ULL;
            }

    int ybase = 2 * h + half - 1;             // input rows ybase+ky (ci = half)
    bool ok0 = (ybase >= 0);                  // only false at h=0, half=0
    bool ok2 = (ybase + 2 < HH);              // only false at h=255, half=1
    bool need_l = (lane == 0)  && (x0 > 0);
    bool need_r = (lane == 31) && (x0 < WW - 8);

    // Fully unrolled mainloop over (c, ky)
    #pragma unroll
    for (int c = 0; c < CIN; c++) {
        const float* xc = xb + (size_t)c * (HH * WW);
        #pragma unroll
        for (int ky = 0; ky < 3; ky++) {
            bool ok = (ky == 0) ? ok0 : ((ky == 2) ? ok2 : true);
            const float* xr = xc + (size_t)(ybase + ky) * WW + x0;
            float4 A = make_float4(0.f, 0.f, 0.f, 0.f);
            float4 Bv = make_float4(0.f, 0.f, 0.f, 0.f);
            float el = 0.f, er = 0.f;
            if (ok) {
                A  = *(const float4*)xr;
                Bv = *(const float4*)(xr + 4);
                if (need_l) el = xr[-1];      // predicated, 1 lane per warp
                if (need_r) er = xr[8];       // predicated, 1 lane per warp
            }
            // Halo exchange via shfl; warp-boundary lanes use the gmem value.
            float vl = __shfl_up_sync(0xffffffffu, Bv.w, 1);
            float vr = __shfl_down_sync(0xffffffffu, A.x, 1);
            if (lane == 0)  vl = el;
            if (lane == 31) vr = er;

            // Input pairs (consecutive columns). even[t]: cols (x0+2t, x0+2t+1)
            // — register-aligned from the float4s (packs should copy-prop away).
            unsigned long long even0 = pack2(A.x, A.y);
            unsigned long long even1 = pack2(A.z, A.w);
            unsigned long long even2 = pack2(Bv.x, Bv.y);
            unsigned long long even3 = pack2(Bv.z, Bv.w);
            // odd[u]: cols (x0+2u-1, x0+2u)
            unsigned long long odd0 = pack2(vl,   A.x);
            unsigned long long odd1 = pack2(A.y,  A.z);
            unsigned long long odd2 = pack2(A.w,  Bv.x);
            unsigned long long odd3 = pack2(Bv.y, Bv.z);
            unsigned long long odd4 = pack2(Bv.w, vr);

            const ulonglong2* wk = (const ulonglong2*)(ws + (c * 3 + ky) * 24);
            #pragma unroll
            for (int kx = 0; kx < 3; kx++) {
                // 4 ulonglong2 = 8 weight f32x2 for this tap: [qq][i], j in .x/.y
                ulonglong2 w00 = wk[kx * 4 + 0];   // qq=0, i=0
                ulonglong2 w01 = wk[kx * 4 + 1];   // qq=0, i=1
                ulonglong2 w10 = wk[kx * 4 + 2];   // qq=1, i=0
                ulonglong2 w11 = wk[kx * 4 + 3];   // qq=1, i=1
                #pragma unroll
                for (int t = 0; t < 4; t++) {
                    // input pair for (t, kx): cols (x0+2t+kx-1, x0+2t+kx)
                    unsigned long long in;
                    if (kx == 1)      in = (t == 0) ? even0 : (t == 1) ? even1 : (t == 2) ? even2 : even3;
                    else if (kx == 0) in = (t == 0) ? odd0  : (t == 1) ? odd1  : (t == 2) ? odd2  : odd3;
                    else              in = (t == 0) ? odd1  : (t == 1) ? odd2  : (t == 2) ? odd3  : odd4;
                    ffma2(acc[t][0][0][0], in, w00.x);
                    ffma2(acc[t][0][0][1], in, w00.y);
                    ffma2(acc[t][0][1][0], in, w01.x);
                    ffma2(acc[t][0][1][1], in, w01.y);
                    ffma2(acc[t][1][0][0], in, w10.x);
                    ffma2(acc[t][1][0][1], in, w10.y);
                    ffma2(acc[t][1][1][0], in, w11.x);
                    ffma2(acc[t][1][1][1], in, w11.y);
                }
            }
        }
    }

    // Store: plane co = half*4 + q; q -> (qq = q&1, sel = q>>1).
    // Col x0+2t+j = lane(sel) of acc[t][qq][i][j].
    #pragma unroll
    for (int q = 0; q < 4; q++) {
        int qq  = q & 1;
        int sel = q >> 1;
        int co  = half * 4 + q;
        #pragma unroll
        for (int i = 0; i < 2; i++) {
            int Y = 2 * h + i;
            float* op = ob + ((size_t)co * HH + Y) * WW + x0;
            float f[8];
            #pragma unroll
            for (int t = 0; t < 4; t++) {
                float s0, s1, u0, u1;
                unpack2(acc[t][qq][i][0], s0, s1);
                unpack2(acc[t][qq][i][1], u0, u1);
                f[2 * t]     = sel ? s1 : s0;
                f[2 * t + 1] = sel ? u1 : u0;
            }
            *(float4*)op       = make_float4(f[0], f[1], f[2], f[3]);
            *(float4*)(op + 4) = make_float4(f[4], f[5], f[6], f[7]);
        }
    }
}

extern "C" void kernel_launch(void* const* d_in, const int* in_sizes, int n_in,
                              void* d_out, int out_size) {
    const float* x = (const float*)d_in[0];
    const float* w = (const float*)d_in[1];
    float* out = (float*)d_out;
    prepack_kernel<<<1, 576>>>(w);
    conv_kernel<<<2048, 128>>>(x, out);
}

// round 16
// speedup vs baseline: 1.3853x; 1.3853x over previous
#include <cuda_runtime.h>
#include <cstdint>

#define CIN 4
#define COUT 8
#define HH 512
#define WW 512

// Prepacked weights: [half][c][ky][kx][co4][i] -> float2 (j=0, j=1 weight rows)
__device__ float2 g_wpk[576];

__global__ void prepack_kernel(const float* __restrict__ w) {
    int idx = threadIdx.x;
    if (idx >= 576) return;
    int i = idx & 1;
    int t = idx >> 1;
    int co4 = t & 3; t >>= 2;
    int kx = t % 3; t /= 3;
    int ky = t % 3; t /= 3;
    int c  = t & 3; t >>= 2;
    int half = t;                       // 0 or 1
    int g  = half * 2 + (co4 >> 1);     // group = co>>1
    int ct = c * 9 + ky * 3 + kx;
    int r0 = (co4 & 1) * 4 + 2 * i;     // weight row for j=0; +1 for j=1
    float2 val;
    val.x = w[(g * 8 + r0) * 36 + ct];
    val.y = w[(g * 8 + r0 + 1) * 36 + ct];
    g_wpk[idx] = val;
}

__device__ __forceinline__ unsigned long long pack2(float a, float b) {
    unsigned long long r;
    asm("mov.b64 %0, {%1, %2};" : "=l"(r) : "f"(a), "f"(b));
    return r;
}
__device__ __forceinline__ void unpack2(unsigned long long p, float& a, float& b) {
    asm("mov.b64 {%0, %1}, %2;" : "=f"(a), "=f"(b) : "l"(p));
}
__device__ __forceinline__ void ffma2(unsigned long long& d, unsigned long long a, unsigned long long b) {
    asm("fma.rn.f32x2 %0, %1, %2, %0;" : "+l"(d) : "l"(a), "l"(b));
}
__device__ __forceinline__ void prefetch_l1(const void* p) {
    asm volatile("prefetch.global.L1 [%0];" :: "l"(p));
}

__global__ __launch_bounds__(128, 4)
void conv_kernel(const float* __restrict__ x, float* __restrict__ out) {
    __shared__ __align__(16) float2 ws[288];
    int tid = threadIdx.x;
    int lane = tid & 31;

    int half  = blockIdx.x & 1;               // channel half (co>>2)
    int hpair = (blockIdx.x >> 1) & 127;      // tile-row pair 0..127
    int b     = blockIdx.x >> 8;              // batch 0..7

    int tx   = tid & 63;                      // 64 threads span one tile-row
    int hsub = tid >> 6;                      // 2 tile-rows per block
    int h    = hpair * 2 + hsub;              // tile row 0..255
    int x0   = tx << 3;                       // 8 output/input columns per thread

    const float* xb = x + (size_t)b * (CIN * HH * WW);
    float*       ob = out + (size_t)b * (COUT * HH * WW);

    int ybase = 2 * h + half - 1;             // input rows ybase+ky (ci = half)
    bool ok0 = (ybase >= 0);                  // only false at h=0, half=0
    bool ok2 = (ybase + 2 < HH);              // only false at h=255, half=1

    // Warm L1 for all 12 input rows this thread will read. Prefetch has no
    // destination register, so MLP=12 regardless of the register budget.
    // Lanes stride 32B -> a warp collectively touches every 128B line of the row.
    #pragma unroll
    for (int c = 0; c < CIN; c++) {
        #pragma unroll
        for (int ky = 0; ky < 3; ky++) {
            int row = ybase + ky;
            int rcl = row < 0 ? 0 : (row > HH - 1 ? HH - 1 : row);  // safe hint addr
            prefetch_l1(xb + (size_t)c * (HH * WW) + (size_t)rcl * WW + x0);
        }
    }

    // Load this half's weights (288 float2 = 2.25 KB) — overlaps the prefetches.
    {
        const float2* src = g_wpk + half * 288;
        for (int k = tid; k < 288; k += 128) ws[k] = src[k];
    }
    __syncthreads();

    // acc[t][co4][i] = f32x2 (out col x0+2t+0, x0+2t+1) at output row 2h+i
    unsigned long long acc[4][4][2];
    #pragma unroll
    for (int t = 0; t < 4; t++)
        #pragma unroll
        for (int q = 0; q < 4; q++) {
            acc[t][q][0] = 0ULL;
            acc[t][q][1] = 0ULL;
        }

    // Halo ownership: halos come from neighbor lanes via shfl; only
    // warp-boundary lanes touch gmem (or are image edge -> 0).
    bool need_l = (lane == 0)  && (x0 > 0);
    bool need_r = (lane == 31) && (x0 < WW - 8);

    // Fully unrolled mainloop over (c, ky).
    #pragma unroll
    for (int c = 0; c < CIN; c++) {
        const float* xc = xb + (size_t)c * (HH * WW);
        #pragma unroll
        for (int ky = 0; ky < 3; ky++) {
            bool ok = (ky == 0) ? ok0 : ((ky == 2) ? ok2 : true);
            const float* xr = xc + (size_t)(ybase + ky) * WW + x0;
            float4 A = make_float4(0.f, 0.f, 0.f, 0.f);
            float4 Bv = make_float4(0.f, 0.f, 0.f, 0.f);
            float el = 0.f, er = 0.f;
            if (ok) {
                A  = *(const float4*)xr;
                Bv = *(const float4*)(xr + 4);
                if (need_l) el = xr[-1];      // predicated, 1 lane per warp
                if (need_r) er = xr[8];       // predicated, 1 lane per warp
            }
            // Halo exchange: vl = prev lane's Bv.w, vr = next lane's A.x
            float vl = __shfl_up_sync(0xffffffffu, Bv.w, 1);
            float vr = __shfl_down_sync(0xffffffffu, A.x, 1);
            if (lane == 0)  vl = el;
            if (lane == 31) vr = er;

            // vv[m] = (v,v) packed; v[m] = input at column x0-1+m  (m = 0..9)
            unsigned long long vv[10];
            vv[0] = pack2(vl, vl);
            vv[1] = pack2(A.x, A.x);   vv[2] = pack2(A.y, A.y);
            vv[3] = pack2(A.z, A.z);   vv[4] = pack2(A.w, A.w);
            vv[5] = pack2(Bv.x, Bv.x); vv[6] = pack2(Bv.y, Bv.y);
            vv[7] = pack2(Bv.z, Bv.z); vv[8] = pack2(Bv.w, Bv.w);
            vv[9] = pack2(vr, vr);

            const ulonglong2* wk = (const ulonglong2*)(ws + (c * 3 + ky) * 24);
            #pragma unroll
            for (int kx = 0; kx < 3; kx++) {
                // 8 weight f32x2 for this tap: [co4][i], warp-uniform broadcast LDS.128
                ulonglong2 q0 = wk[kx * 4 + 0];
                ulonglong2 q1 = wk[kx * 4 + 1];
                ulonglong2 q2 = wk[kx * 4 + 2];
                ulonglong2 q3 = wk[kx * 4 + 3];
                #pragma unroll
                for (int t = 0; t < 4; t++) {
                    int m = 2 * t + kx;              // cj=0 channels
                    ffma2(acc[t][0][0], vv[m],     q0.x);
                    ffma2(acc[t][0][1], vv[m],     q0.y);
                    ffma2(acc[t][1][0], vv[m],     q1.x);
                    ffma2(acc[t][1][1], vv[m],     q1.y);
                    ffma2(acc[t][2][0], vv[m + 1], q2.x);  // cj=1 channels
                    ffma2(acc[t][2][1], vv[m + 1], q2.y);
                    ffma2(acc[t][3][0], vv[m + 1], q3.x);
                    ffma2(acc[t][3][1], vv[m + 1], q3.y);
                }
            }
        }
    }

    // Store: per (co, i): 8 contiguous columns -> two coalesced float4s
    #pragma unroll
    for (int q = 0; q < 4; q++) {
        int co = half * 4 + q;
        #pragma unroll
        for (int i = 0; i < 2; i++) {
            int Y = 2 * h + i;
            float* op = ob + ((size_t)co * HH + Y) * WW + x0;
            float a0, a1, a2, a3, a4, a5, a6, a7;
            unpack2(acc[0][q][i], a0, a1);
            unpack2(acc[1][q][i], a2, a3);
            unpack2(acc[2][q][i], a4, a5);
            unpack2(acc[3][q][i], a6, a7);
            *(float4*)op       = make_float4(a0, a1, a2, a3);
            *(float4*)(op + 4) = make_float4(a4, a5, a6, a7);
        }
    }
}

extern "C" void kernel_launch(void* const* d_in, const int* in_sizes, int n_in,
                              void* d_out, int out_size) {
    const float* x = (const float*)d_in[0];
    const float* w = (const float*)d_in[1];
    float* out = (float*)d_out;
    prepack_kernel<<<1, 576>>>(w);
    conv_kernel<<<2048, 128>>>(x, out);
}

// round 17
// speedup vs baseline: 1.3889x; 1.0026x over previous
#include <cuda_runtime.h>
#include <cstdint>

#define CIN 4
#define COUT 8
#define HH 512
#define WW 512

// Prepacked weights: [half][c][ky][kx][co4][i] -> float2 (j=0, j=1 weight rows)
__device__ float2 g_wpk[576];

__global__ void prepack_kernel(const float* __restrict__ w) {
    int idx = threadIdx.x;
    if (idx >= 576) return;
    int i = idx & 1;
    int t = idx >> 1;
    int co4 = t & 3; t >>= 2;
    int kx = t % 3; t /= 3;
    int ky = t % 3; t /= 3;
    int c  = t & 3; t >>= 2;
    int half = t;                       // 0 or 1
    int g  = half * 2 + (co4 >> 1);     // group = co>>1
    int ct = c * 9 + ky * 3 + kx;
    int r0 = (co4 & 1) * 4 + 2 * i;     // weight row for j=0; +1 for j=1
    float2 val;
    val.x = w[(g * 8 + r0) * 36 + ct];
    val.y = w[(g * 8 + r0 + 1) * 36 + ct];
    g_wpk[idx] = val;
}

__device__ __forceinline__ unsigned long long pack2(float a, float b) {
    unsigned long long r;
    asm("mov.b64 %0, {%1, %2};" : "=l"(r) : "f"(a), "f"(b));
    return r;
}
__device__ __forceinline__ void unpack2(unsigned long long p, float& a, float& b) {
    asm("mov.b64 {%0, %1}, %2;" : "=f"(a), "=f"(b) : "l"(p));
}
__device__ __forceinline__ void ffma2(unsigned long long& d, unsigned long long a, unsigned long long b) {
    asm("fma.rn.f32x2 %0, %1, %2, %0;" : "+l"(d) : "l"(a), "l"(b));
}
__device__ __forceinline__ void cp16(void* smem_dst, const void* gsrc) {
    unsigned s = (unsigned)__cvta_generic_to_shared(smem_dst);
    asm volatile("cp.async.ca.shared.global [%0], [%1], 16;" :: "r"(s), "l"(gsrc));
}

__global__ __launch_bounds__(128, 4)
void conv_kernel(const float* __restrict__ x, float* __restrict__ out) {
    // Input stage: 4 channels x 5 rows x 512 cols = 40 KB (as float4)
    __shared__ __align__(16) float4 sx4[4 * 5 * 128];
    __shared__ __align__(16) float2 ws[288];
    int tid = threadIdx.x;
    int lane = tid & 31;

    int half  = blockIdx.x & 1;               // channel half (co>>2)
    int hpair = (blockIdx.x >> 1) & 127;      // tile-row pair 0..127
    int b     = blockIdx.x >> 8;              // batch 0..7

    const float* xb = x + (size_t)b * (CIN * HH * WW);
    float*       ob = out + (size_t)b * (COUT * HH * WW);

    // Rows ybase0 .. ybase0+4 cover both tile rows of this block.
    int ybase0 = 4 * hpair + half - 1;

    // Stage input rows into smem: 20 independent cp.async per thread (MLP=20).
    #pragma unroll
    for (int c = 0; c < CIN; c++) {
        #pragma unroll
        for (int r = 0; r < 5; r++) {
            int row = ybase0 + r;
            float4* dst = &sx4[(c * 5 + r) * 128 + tid];
            if ((unsigned)row < (unsigned)HH) {
                const float4* src = (const float4*)(xb + (size_t)c * (HH * WW)
                                                       + (size_t)row * WW) + tid;
                cp16(dst, src);
            } else {
                *dst = make_float4(0.f, 0.f, 0.f, 0.f);   // zero-fill OOB row
            }
        }
    }
    asm volatile("cp.async.commit_group;");

    // Load this half's weights (288 float2 = 2.25 KB) while cp.async is in flight.
    {
        const float2* src = g_wpk + half * 288;
        for (int k = tid; k < 288; k += 128) ws[k] = src[k];
    }
    asm volatile("cp.async.wait_group 0;" ::: "memory");
    __syncthreads();

    int tx   = tid & 63;                      // 64 threads span one tile-row
    int hsub = tid >> 6;                      // 2 tile-rows per block
    int h    = hpair * 2 + hsub;              // tile row 0..255
    int x0   = tx << 3;                       // 8 output/input columns per thread

    // acc[t][co4][i] = f32x2 (out col x0+2t+0, x0+2t+1) at output row 2h+i
    unsigned long long acc[4][4][2];
    #pragma unroll
    for (int t = 0; t < 4; t++)
        #pragma unroll
        for (int q = 0; q < 4; q++) {
            acc[t][q][0] = 0ULL;
            acc[t][q][1] = 0ULL;
        }

    // Halo ownership: halos come from neighbor lanes via shfl; warp-boundary
    // lanes read the smem scalar (image edges stay 0).
    bool need_l = (lane == 0)  && (x0 > 0);
    bool need_r = (lane == 31) && (x0 < WW - 8);
    const float* sxf = (const float*)sx4;
    int rbase = 2 * hsub;                     // smem row = rbase + ky

    // Fully unrolled mainloop over (c, ky): all reads hit smem (29-cyc LDS).
    #pragma unroll
    for (int c = 0; c < CIN; c++) {
        #pragma unroll
        for (int ky = 0; ky < 3; ky++) {
            int ri = (c * 5 + rbase + ky) * 128;
            float4 A  = sx4[ri + 2 * tx];
            float4 Bv = sx4[ri + 2 * tx + 1];
            float el = 0.f, er = 0.f;
            if (need_l) el = sxf[ri * 4 + x0 - 1];   // 1 lane per warp
            if (need_r) er = sxf[ri * 4 + x0 + 8];   // 1 lane per warp
            // Halo exchange: vl = prev lane's Bv.w, vr = next lane's A.x
            float vl = __shfl_up_sync(0xffffffffu, Bv.w, 1);
            float vr = __shfl_down_sync(0xffffffffu, A.x, 1);
            if (lane == 0)  vl = el;
            if (lane == 31) vr = er;

            // vv[m] = (v,v) packed; v[m] = input at column x0-1+m  (m = 0..9)
            unsigned long long vv[10];
            vv[0] = pack2(vl, vl);
            vv[1] = pack2(A.x, A.x);   vv[2] = pack2(A.y, A.y);
            vv[3] = pack2(A.z, A.z);   vv[4] = pack2(A.w, A.w);
            vv[5] = pack2(Bv.x, Bv.x); vv[6] = pack2(Bv.y, Bv.y);
            vv[7] = pack2(Bv.z, Bv.z); vv[8] = pack2(Bv.w, Bv.w);
            vv[9] = pack2(vr, vr);

            const ulonglong2* wk = (const ulonglong2*)(ws + (c * 3 + ky) * 24);
            #pragma unroll
            for (int kx = 0; kx < 3; kx++) {
                // 8 weight f32x2 for this tap: [co4][i], warp-uniform broadcast LDS.128
                ulonglong2 q0 = wk[kx * 4 + 0];
                ulonglong2 q1 = wk[kx * 4 + 1];
                ulonglong2 q2 = wk[kx * 4 + 2];
                ulonglong2 q3 = wk[kx * 4 + 3];
                #pragma unroll
                for (int t = 0; t < 4; t++) {
                    int m = 2 * t + kx;              // cj=0 channels
                    ffma2(acc[t][0][0], vv[m],     q0.x);
                    ffma2(acc[t][0][1], vv[m],     q0.y);
                    ffma2(acc[t][1][0], vv[m],     q1.x);
                    ffma2(acc[t][1][1], vv[m],     q1.y);
                    ffma2(acc[t][2][0], vv[m + 1], q2.x);  // cj=1 channels
                    ffma2(acc[t][2][1], vv[m + 1], q2.y);
                    ffma2(acc[t][3][0], vv[m + 1], q3.x);
                    ffma2(acc[t][3][1], vv[m + 1], q3.y);
                }
            }
        }
    }

    // Store: per (co, i): 8 contiguous columns -> two coalesced float4s
    #pragma unroll
    for (int q = 0; q < 4; q++) {
        int co = half * 4 + q;
        #pragma unroll
        for (int i = 0; i < 2; i++) {
            int Y = 2 * h + i;
            float* op = ob + ((size_t)co * HH + Y) * WW + x0;
            float a0, a1, a2, a3, a4, a5, a6, a7;
            unpack2(acc[0][q][i], a0, a1);
            unpack2(acc[1][q][i], a2, a3);
            unpack2(acc[2][q][i], a4, a5);
            unpack2(acc[3][q][i], a6, a7);
            *(float4*)op       = make_float4(a0, a1, a2, a3);
            *(float4*)(op + 4) = make_float4(a4, a5, a6, a7);
        }
    }
}

extern "C" void kernel_launch(void* const* d_in, const int* in_sizes, int n_in,
                              void* d_out, int out_size) {
    const float* x = (const float*)d_in[0];
    const float* w = (const float*)d_in[1];
    float* out = (float*)d_out;
    prepack_kernel<<<1, 576>>>(w);
    conv_kernel<<<2048, 128>>>(x, out);
}